// round 2
// baseline (speedup 1.0000x reference)
#include <cuda_runtime.h>
#include <math.h>

#define NB 2
#define NS 2048
#define ND 1024
#define NH 16
#define NHD 64
#define NBS (NB*NS)        // 4096
#define THREE_D (3*ND)     // 3072

// ------------------------- scratch (allocation-free) -------------------------
__device__ float g_h[NBS*ND];
__device__ float g_qkv[NBS*THREE_D];
__device__ float g_qh[NB*NH*NS*NHD];
__device__ float g_kh[NB*NH*NS*NHD];
__device__ float g_vh[NB*NH*NS*NHD];
__device__ float g_attn[NBS*ND];
__device__ float g_attnproj[NBS*ND];
__device__ float g_x1[NBS*ND];
__device__ float g_h2[NBS*ND];
__device__ float g_gv[NBS*8*ND];
__device__ float g_t[NBS*4*ND];
__device__ float g_Q[NHD*NHD];
__device__ float g_cos[NS*NHD];
__device__ float g_sin[NS*NHD];

// ------------------------------- rmsnorm ------------------------------------
__global__ __launch_bounds__(256)
void rmsnorm_kernel(const float* __restrict__ x, float* __restrict__ o) {
    int row = blockIdx.x;
    const float4* xr = (const float4*)(x + (size_t)row * ND);
    float4 v = xr[threadIdx.x];
    float ss = v.x*v.x + v.y*v.y + v.z*v.z + v.w*v.w;
    #pragma unroll
    for (int m = 16; m > 0; m >>= 1) ss += __shfl_xor_sync(0xffffffffu, ss, m);
    __shared__ float sred[8];
    if ((threadIdx.x & 31) == 0) sred[threadIdx.x >> 5] = ss;
    __syncthreads();
    float tot = 0.f;
    #pragma unroll
    for (int i = 0; i < 8; i++) tot += sred[i];
    float r = rsqrtf(tot * (1.0f / ND) + 1e-6f);
    float4 ov = make_float4(v.x*r, v.y*r, v.z*r, v.w*r);
    ((float4*)(o + (size_t)row * ND))[threadIdx.x] = ov;
}

// ----------------------- Householder Q (64x64) ------------------------------
__global__ void buildQ_kernel(const float* __restrict__ vs) {
    __shared__ float Qm[NHD][NHD];   // each thread owns column t
    __shared__ float vv[NHD];
    int t = threadIdx.x;             // 64 threads
    #pragma unroll
    for (int i = 0; i < NHD; i++) Qm[i][t] = (i == t) ? 1.f : 0.f;
    for (int r = 0; r < 32; r++) {
        __syncthreads();             // protect vv rewrite vs prior reads
        vv[t] = vs[r * NHD + t];
        __syncthreads();
        float w = 0.f, vn = 0.f;
        #pragma unroll
        for (int i = 0; i < NHD; i++) { w += vv[i] * Qm[i][t]; vn += vv[i] * vv[i]; }
        float c = 2.0f / (vn + 1e-8f);
        #pragma unroll
        for (int i = 0; i < NHD; i++) Qm[i][t] -= c * vv[i] * w;
    }
    __syncthreads();
    for (int i = 0; i < NHD; i++) g_Q[i * NHD + t] = Qm[i][t];
}

// ----------------------------- rope tables ----------------------------------
__global__ void rope_tables_kernel() {
    int s = blockIdx.x;
    int d = threadIdx.x;             // 64
    int i = d & 31;
    float invf = powf(10000.0f, -(float)(2 * i) / 64.0f);
    float ang = (float)s * invf;
    g_cos[s * NHD + d] = cosf(ang);
    g_sin[s * NHD + d] = sinf(ang);
}

// ------------- RnRoPE apply + head transpose (q,k rotated, v copied) --------
__global__ __launch_bounds__(256)
void rope_apply_kernel(const float* __restrict__ qkv) {
    int bs = blockIdx.x;             // b*S + s
    int which = blockIdx.y;          // 0:q 1:k 2:v
    int b = bs >> 11, s = bs & 2047;
    int tid = threadIdx.x;
    int lane = tid & 63, grp = tid >> 6;   // 4 groups of 64

    if (which == 2) {
        #pragma unroll
        for (int hh = 0; hh < 4; hh++) {
            int h = grp * 4 + hh;
            g_vh[(((size_t)(b * NH + h)) * NS + s) * NHD + lane] =
                qkv[(size_t)bs * THREE_D + 2 * ND + h * NHD + lane];
        }
        return;
    }

    __shared__ float Qm[NHD][NHD + 1];
    __shared__ float xb[4][NHD];
    __shared__ float rb[4][NHD];
    __shared__ float cs[NHD], sn[NHD];
    for (int i = tid; i < NHD * NHD; i += 256) Qm[i >> 6][i & 63] = g_Q[i];
    if (tid < NHD) { cs[tid] = g_cos[s * NHD + tid]; sn[tid] = g_sin[s * NHD + tid]; }
    __syncthreads();

    const float* src = qkv + (size_t)bs * THREE_D + which * ND;
    float* dst = (which == 0) ? g_qh : g_kh;

    for (int hh = 0; hh < 4; hh++) {
        int h = grp * 4 + hh;
        xb[grp][lane] = src[h * NHD + lane];
        __syncthreads();
        float t = 0.f;                      // (x @ Q^T)[lane]
        #pragma unroll
        for (int j = 0; j < NHD; j++) t += xb[grp][j] * Qm[lane][j];
        rb[grp][lane] = t;
        __syncthreads();
        float rot = (lane < 32) ? -rb[grp][lane + 32] : rb[grp][lane - 32];
        float r = t * cs[lane] + rot * sn[lane];
        xb[grp][lane] = r;
        __syncthreads();
        float o = 0.f;                      // (r @ Q)[lane]
        #pragma unroll
        for (int j = 0; j < NHD; j++) o += xb[grp][j] * Qm[j][lane];
        dst[(((size_t)(b * NH + h)) * NS + s) * NHD + lane] = o;
        __syncthreads();
    }
}

// ------------------------------ flash attention -----------------------------
// BM=BN=64, HD=64; block-causal mask -> per q-tile, kv tiles fully dense.
#define FL_STRIDE 68
#define FLASH_SMEM (4 * 64 * FL_STRIDE * 4)

__global__ __launch_bounds__(256)
void flash_kernel() {
    extern __shared__ float smf[];
    float* QsT = smf;                      // [d][r], stride 68
    float* KsT = smf + 64 * FL_STRIDE;     // [d][c]
    float* Vs  = smf + 2 * 64 * FL_STRIDE; // [n][d]
    float* Ps  = smf + 3 * 64 * FL_STRIDE; // [r][n]

    const int qt = blockIdx.x;             // 0..31
    const int bh = blockIdx.y;             // 0..31
    const int b = bh >> 4, h = bh & 15;
    const int tid = threadIdx.x;
    const int ty = tid >> 4, tx = tid & 15;
    const int lr = tid >> 2;               // 0..63
    const int lc = (tid & 3) * 16;

    const float* qbase = g_qh + ((size_t)bh * NS + qt * 64) * NHD;
    const float* kbase = g_kh + (size_t)bh * NS * NHD;
    const float* vbase = g_vh + (size_t)bh * NS * NHD;

    #pragma unroll
    for (int v4 = 0; v4 < 4; v4++) {
        float4 q4 = *(const float4*)(qbase + lr * 64 + lc + v4 * 4);
        QsT[(lc + v4*4 + 0) * FL_STRIDE + lr] = q4.x;
        QsT[(lc + v4*4 + 1) * FL_STRIDE + lr] = q4.y;
        QsT[(lc + v4*4 + 2) * FL_STRIDE + lr] = q4.z;
        QsT[(lc + v4*4 + 3) * FL_STRIDE + lr] = q4.w;
    }

    float m[4], l[4], o[4][4];
    #pragma unroll
    for (int i = 0; i < 4; i++) {
        m[i] = -1e30f; l[i] = 0.f;
        #pragma unroll
        for (int j = 0; j < 4; j++) o[i][j] = 0.f;
    }

    const int nkv = ((qt >> 1) + 1) * 2;   // kv tiles of 64 allowed by block-causal mask
    for (int kt = 0; kt < nkv; kt++) {
        __syncthreads();   // covers QsT init / prior-iter Ps,Vs reads
        const float* kp = kbase + (size_t)kt * 64 * 64;
        const float* vp = vbase + (size_t)kt * 64 * 64;
        #pragma unroll
        for (int v4 = 0; v4 < 4; v4++) {
            float4 k4 = *(const float4*)(kp + lr * 64 + lc + v4 * 4);
            KsT[(lc + v4*4 + 0) * FL_STRIDE + lr] = k4.x;
            KsT[(lc + v4*4 + 1) * FL_STRIDE + lr] = k4.y;
            KsT[(lc + v4*4 + 2) * FL_STRIDE + lr] = k4.z;
            KsT[(lc + v4*4 + 3) * FL_STRIDE + lr] = k4.w;
            float4 vv4 = *(const float4*)(vp + lr * 64 + lc + v4 * 4);
            *(float4*)&Vs[lr * FL_STRIDE + lc + v4 * 4] = vv4;
        }
        __syncthreads();

        float s4[4][4];
        #pragma unroll
        for (int i = 0; i < 4; i++)
            #pragma unroll
            for (int j = 0; j < 4; j++) s4[i][j] = 0.f;

        #pragma unroll 8
        for (int d = 0; d < 64; d++) {
            float4 av = *(const float4*)&QsT[d * FL_STRIDE + ty * 4];
            float4 bv = *(const float4*)&KsT[d * FL_STRIDE + tx * 4];
            float a[4] = {av.x, av.y, av.z, av.w};
            float c[4] = {bv.x, bv.y, bv.z, bv.w};
            #pragma unroll
            for (int i = 0; i < 4; i++)
                #pragma unroll
                for (int j = 0; j < 4; j++)
                    s4[i][j] = fmaf(a[i], c[j], s4[i][j]);
        }

        const float scale = 0.125f;  // 1/sqrt(64)
        #pragma unroll
        for (int i = 0; i < 4; i++) {
            float mt = -1e30f;
            #pragma unroll
            for (int j = 0; j < 4; j++) { s4[i][j] *= scale; mt = fmaxf(mt, s4[i][j]); }
            #pragma unroll
            for (int msk = 8; msk > 0; msk >>= 1)
                mt = fmaxf(mt, __shfl_xor_sync(0xffffffffu, mt, msk));
            float mn = fmaxf(m[i], mt);
            float alpha = __expf(m[i] - mn);
            m[i] = mn;
            float lt = 0.f;
            #pragma unroll
            for (int j = 0; j < 4; j++) {
                float p = __expf(s4[i][j] - mn);
                s4[i][j] = p; lt += p;
            }
            #pragma unroll
            for (int msk = 8; msk > 0; msk >>= 1)
                lt += __shfl_xor_sync(0xffffffffu, lt, msk);
            l[i] = l[i] * alpha + lt;
            #pragma unroll
            for (int j = 0; j < 4; j++) o[i][j] *= alpha;
            float4 pw = make_float4(s4[i][0], s4[i][1], s4[i][2], s4[i][3]);
            *(float4*)&Ps[(ty * 4 + i) * FL_STRIDE + tx * 4] = pw;
        }
        __syncthreads();

        #pragma unroll 8
        for (int n = 0; n < 64; n++) {
            float4 vv = *(const float4*)&Vs[n * FL_STRIDE + tx * 4];
            float c[4] = {vv.x, vv.y, vv.z, vv.w};
            float pa[4];
            #pragma unroll
            for (int i = 0; i < 4; i++) pa[i] = Ps[(ty * 4 + i) * FL_STRIDE + n];
            #pragma unroll
            for (int i = 0; i < 4; i++)
                #pragma unroll
                for (int j = 0; j < 4; j++)
                    o[i][j] = fmaf(pa[i], c[j], o[i][j]);
        }
    }

    const int s0 = qt * 64;
    #pragma unroll
    for (int i = 0; i < 4; i++) {
        float inv = 1.f / l[i];
        int srow = s0 + ty * 4 + i;
        float4 ov = make_float4(o[i][0]*inv, o[i][1]*inv, o[i][2]*inv, o[i][3]*inv);
        *(float4*)(g_attn + ((size_t)(b * NS + srow)) * ND + h * 64 + tx * 4) = ov;
    }
}

// ---------------------------------- SGEMM -----------------------------------
// C[M,N] = A[M,K] @ B[K,N]  (row-major), BM=BN=128, BK=8, 8x8 microtiles.
// EPI 0: +bias (optional)     EPI 1: C = e2 + e1*sigmoid(acc+bias)
// EPI 2: C = e2 + acc + bias
template<int EPI>
__global__ __launch_bounds__(256, 2)
void sgemm_kernel(const float* __restrict__ A, const float* __restrict__ Bm,
                  float* __restrict__ C, int M, int N, int K,
                  const float* __restrict__ bias,
                  const float* __restrict__ e1, const float* __restrict__ e2)
{
    __shared__ float As[8][128];
    __shared__ float Bs[8][128];
    const int tid = threadIdx.x;
    const int m0 = blockIdx.y * 128;
    const int n0 = blockIdx.x * 128;
    const int trow = tid >> 4;
    const int tcol = tid & 15;
    const int ar = tid >> 1;
    const int ak = (tid & 1) * 4;
    const int br = tid >> 5;
    const int bc = (tid & 31) * 4;

    const float* Ap = A + (size_t)(m0 + ar) * K + ak;
    const float* Bp = Bm + (size_t)br * N + n0 + bc;

    float acc[8][8];
    #pragma unroll
    for (int i = 0; i < 8; i++)
        #pragma unroll
        for (int j = 0; j < 8; j++) acc[i][j] = 0.f;

    for (int k0 = 0; k0 < K; k0 += 8) {
        float4 a4 = *(const float4*)Ap;
        float4 b4 = *(const float4*)Bp;
        As[ak + 0][ar] = a4.x;
        As[ak + 1][ar] = a4.y;
        As[ak + 2][ar] = a4.z;
        As[ak + 3][ar] = a4.w;
        *(float4*)&Bs[br][bc] = b4;
        __syncthreads();
        #pragma unroll
        for (int kk = 0; kk < 8; kk++) {
            float4 x0 = *(const float4*)&As[kk][trow * 8];
            float4 x1 = *(const float4*)&As[kk][trow * 8 + 4];
            float4 y0 = *(const float4*)&Bs[kk][tcol * 8];
            float4 y1 = *(const float4*)&Bs[kk][tcol * 8 + 4];
            float a[8] = {x0.x, x0.y, x0.z, x0.w, x1.x, x1.y, x1.z, x1.w};
            float b[8] = {y0.x, y0.y, y0.z, y0.w, y1.x, y1.y, y1.z, y1.w};
            #pragma unroll
            for (int i = 0; i < 8; i++)
                #pragma unroll
                for (int j = 0; j < 8; j++)
                    acc[i][j] = fmaf(a[i], b[j], acc[i][j]);
        }
        __syncthreads();
        Ap += 8;
        Bp += (size_t)8 * N;
    }

    #pragma unroll
    for (int i = 0; i < 8; i++) {
        int mrow = m0 + trow * 8 + i;
        size_t base = (size_t)mrow * N + n0 + tcol * 8;
        #pragma unroll
        for (int j = 0; j < 8; j++) {
            size_t idx = base + j;
            int n = n0 + tcol * 8 + j;
            float v = acc[i][j];
            if (EPI == 0) {
                if (bias) v += bias[n];
                C[idx] = v;
            } else if (EPI == 1) {
                float gt = 1.f / (1.f + __expf(-(v + bias[n])));
                C[idx] = e2[idx] + e1[idx] * gt;
            } else {
                C[idx] = e2[idx] + v + bias[n];
            }
        }
    }
}

// ------------------------------- GLU (exact gelu) ---------------------------
__global__ __launch_bounds__(256)
void glu_kernel(const float* __restrict__ gv, float* __restrict__ t) {
    size_t idx = (size_t)blockIdx.x * 256 + threadIdx.x;  // over float4s of [4096, 4096]
    if (idx >= (size_t)NBS * 4 * ND / 4) return;
    size_t row = idx >> 10;           // 1024 float4 per row
    size_t col4 = idx & 1023;
    float4 g4 = ((const float4*)(gv + row * 8 * ND))[col4];
    float4 v4 = ((const float4*)(gv + row * 8 * ND + 4 * ND))[col4];
    const float k = 0.70710678118654752f;
    float4 o;
    o.x = v4.x * (0.5f * g4.x * (1.f + erff(g4.x * k)));
    o.y = v4.y * (0.5f * g4.y * (1.f + erff(g4.y * k)));
    o.z = v4.z * (0.5f * g4.z * (1.f + erff(g4.z * k)));
    o.w = v4.w * (0.5f * g4.w * (1.f + erff(g4.w * k)));
    ((float4*)t)[idx] = o;
}

// --------------------------------- launcher ---------------------------------
extern "C" void kernel_launch(void* const* d_in, const int* in_sizes, int n_in,
                              void* d_out, int out_size) {
    const float* x          = (const float*)d_in[0];
    // d_in[1] = mask (derived analytically), d_in[2] = grid_size (unused)
    const float* vs         = (const float*)d_in[3];
    const float* w_qkv      = (const float*)d_in[4];
    const float* w_out      = (const float*)d_in[5];
    const float* w_gate     = (const float*)d_in[6];
    const float* b_gate     = (const float*)d_in[7];
    const float* w_mlp_gate = (const float*)d_in[8];
    const float* b_mlp_gate = (const float*)d_in[9];
    const float* w_mlp_out  = (const float*)d_in[10];
    const float* b_mlp_out  = (const float*)d_in[11];
    float* out = (float*)d_out;

    float *p_h, *p_qkv, *p_attn, *p_attnproj, *p_x1, *p_h2, *p_gv, *p_t;
    cudaGetSymbolAddress((void**)&p_h, g_h);
    cudaGetSymbolAddress((void**)&p_qkv, g_qkv);
    cudaGetSymbolAddress((void**)&p_attn, g_attn);
    cudaGetSymbolAddress((void**)&p_attnproj, g_attnproj);
    cudaGetSymbolAddress((void**)&p_x1, g_x1);
    cudaGetSymbolAddress((void**)&p_h2, g_h2);
    cudaGetSymbolAddress((void**)&p_gv, g_gv);
    cudaGetSymbolAddress((void**)&p_t, g_t);

    static_assert(FLASH_SMEM == 69632, "smem size");
    cudaFuncSetAttribute(flash_kernel, cudaFuncAttributeMaxDynamicSharedMemorySize, FLASH_SMEM);

    // 1. h = rmsnorm(x)
    rmsnorm_kernel<<<NBS, 256>>>(x, p_h);
    // 2. Householder Q ; 3. rope tables
    buildQ_kernel<<<1, 64>>>(vs);
    rope_tables_kernel<<<NS, 64>>>();
    // 4. qkv = h @ w_qkv
    sgemm_kernel<0><<<dim3(THREE_D / 128, NBS / 128), 256>>>(
        p_h, w_qkv, p_qkv, NBS, THREE_D, ND, nullptr, nullptr, nullptr);
    // 5. RnRoPE + head transpose
    rope_apply_kernel<<<dim3(NBS, 3), 256>>>(p_qkv);
    // 6. attention -> g_attn [B,S,D]
    flash_kernel<<<dim3(NS / 64, NB * NH), 256, FLASH_SMEM>>>();
    // 7. attnproj = attn @ w_out
    sgemm_kernel<0><<<dim3(ND / 128, NBS / 128), 256>>>(
        p_attn, w_out, p_attnproj, NBS, ND, ND, nullptr, nullptr, nullptr);
    // 8. x1 = x + attnproj * sigmoid(attnproj @ w_gate + b_gate)
    sgemm_kernel<1><<<dim3(ND / 128, NBS / 128), 256>>>(
        p_attnproj, w_gate, p_x1, NBS, ND, ND, b_gate, p_attnproj, x);
    // 9. h2 = rmsnorm(x1)
    rmsnorm_kernel<<<NBS, 256>>>(p_x1, p_h2);
    // 10. gv = h2 @ w_mlp_gate + b_mlp_gate
    sgemm_kernel<0><<<dim3(8 * ND / 128, NBS / 128), 256>>>(
        p_h2, w_mlp_gate, p_gv, NBS, 8 * ND, ND, b_mlp_gate, nullptr, nullptr);
    // 11. t = val * gelu(g)
    glu_kernel<<<(NBS * 4 * ND / 4) / 256, 256>>>(p_gv, p_t);
    // 12. out = x1 + t @ w_mlp_out + b_mlp_out
    sgemm_kernel<2><<<dim3(ND / 128, NBS / 128), 256>>>(
        p_t, w_mlp_out, out, NBS, ND, 4 * ND, b_mlp_out, nullptr, p_x1);
}

// round 4
// speedup vs baseline: 1.8138x; 1.8138x over previous
#include <cuda_runtime.h>
#include <cuda_bf16.h>
#include <cstdint>
#include <math.h>

#define NB 2
#define NS 2048
#define ND 1024
#define NH 16
#define NHD 64
#define NBS (NB*NS)        // 4096
#define THREE_D (3*ND)     // 3072

// ===================== helpers ==============================================
__device__ __forceinline__ uint32_t smem_u32(const void* p) {
    uint32_t a;
    asm("{ .reg .u64 t; cvta.to.shared.u64 t, %1; cvt.u32.u64 %0, t; }" : "=r"(a) : "l"(p));
    return a;
}
__device__ __forceinline__ void cp_async16(uint32_t s, const void* g) {
    asm volatile("cp.async.cg.shared.global [%0], [%1], 16;" :: "r"(s), "l"(g));
}
#define CP_COMMIT() asm volatile("cp.async.commit_group;" ::: "memory")
#define CP_WAIT1()  asm volatile("cp.async.wait_group 1;" ::: "memory")

__device__ __forceinline__ void ldsm_x4(uint32_t& r0, uint32_t& r1, uint32_t& r2, uint32_t& r3,
                                        uint32_t addr) {
    asm volatile("ldmatrix.sync.aligned.m8n8.x4.shared.b16 {%0,%1,%2,%3}, [%4];"
                 : "=r"(r0), "=r"(r1), "=r"(r2), "=r"(r3) : "r"(addr));
}
__device__ __forceinline__ void mma16816(float* d, const uint32_t* a, uint32_t b0, uint32_t b1) {
    asm volatile(
        "mma.sync.aligned.m16n8k16.row.col.f32.bf16.bf16.f32 "
        "{%0,%1,%2,%3}, {%4,%5,%6,%7}, {%8,%9}, {%0,%1,%2,%3};"
        : "+f"(d[0]), "+f"(d[1]), "+f"(d[2]), "+f"(d[3])
        : "r"(a[0]), "r"(a[1]), "r"(a[2]), "r"(a[3]), "r"(b0), "r"(b1));
}

// ------------------------- scratch (allocation-free) -------------------------
__device__ float g_qkv[NBS*THREE_D];
__device__ float g_qh[NB*NH*NS*NHD];
__device__ float g_kh[NB*NH*NS*NHD];
__device__ float g_vh[NB*NH*NS*NHD];
__device__ float g_attnproj[NBS*ND];
__device__ float g_x1[NBS*ND];
__device__ float g_gv[NBS*8*ND];
__device__ float g_Q[NHD*NHD];
__device__ float g_cos[NS*NHD];
__device__ float g_sin[NS*NHD];
// augmented split-bf16 activations: [M, 3K] = [hi | lo | hi]
__device__ __nv_bfloat16 g_h_aug[NBS*3*ND];
__device__ __nv_bfloat16 g_attn_aug[NBS*3*ND];
__device__ __nv_bfloat16 g_ap_aug[NBS*3*ND];
__device__ __nv_bfloat16 g_h2_aug[NBS*3*ND];
__device__ __nv_bfloat16 g_t_aug[(size_t)NBS*12*ND];
// augmented transposed weights: [N, 3K] = [hi | hi | lo]
__device__ __nv_bfloat16 g_wqkvT[3*ND*3*ND];
__device__ __nv_bfloat16 g_woutT[ND*3*ND];
__device__ __nv_bfloat16 g_wgateT[ND*3*ND];
__device__ __nv_bfloat16 g_wmgT[(size_t)8*ND*3*ND];
__device__ __nv_bfloat16 g_wmoT[(size_t)ND*12*ND];

// ======================= split helpers ======================================
__device__ __forceinline__ void split_hi_lo(float v, __nv_bfloat16& hi, __nv_bfloat16& lo) {
    hi = __float2bfloat16(v);
    lo = __float2bfloat16(v - __bfloat162float(hi));
}
__device__ __forceinline__ void store_aug4(__nv_bfloat16* base, size_t rowbase, int K, int col,
                                           float v0, float v1, float v2, float v3) {
    __nv_bfloat16 h[4], l[4];
    split_hi_lo(v0, h[0], l[0]); split_hi_lo(v1, h[1], l[1]);
    split_hi_lo(v2, h[2], l[2]); split_hi_lo(v3, h[3], l[3]);
    __nv_bfloat162 p;
    p.x = h[0]; p.y = h[1]; *(__nv_bfloat162*)(base + rowbase + col) = p;
    p.x = h[2]; p.y = h[3]; *(__nv_bfloat162*)(base + rowbase + col + 2) = p;
    p.x = l[0]; p.y = l[1]; *(__nv_bfloat162*)(base + rowbase + K + col) = p;
    p.x = l[2]; p.y = l[3]; *(__nv_bfloat162*)(base + rowbase + K + col + 2) = p;
    p.x = h[0]; p.y = h[1]; *(__nv_bfloat162*)(base + rowbase + 2*K + col) = p;
    p.x = h[2]; p.y = h[3]; *(__nv_bfloat162*)(base + rowbase + 2*K + col + 2) = p;
}

// ------------------------- rmsnorm -> aug bf16 ------------------------------
__global__ __launch_bounds__(256)
void rmsnorm_split_kernel(const float* __restrict__ x, __nv_bfloat16* __restrict__ o) {
    int row = blockIdx.x;
    const float4* xr = (const float4*)(x + (size_t)row * ND);
    float4 v = xr[threadIdx.x];
    float ss = v.x*v.x + v.y*v.y + v.z*v.z + v.w*v.w;
    #pragma unroll
    for (int m = 16; m > 0; m >>= 1) ss += __shfl_xor_sync(0xffffffffu, ss, m);
    __shared__ float sred[8];
    if ((threadIdx.x & 31) == 0) sred[threadIdx.x >> 5] = ss;
    __syncthreads();
    float tot = 0.f;
    #pragma unroll
    for (int i = 0; i < 8; i++) tot += sred[i];
    float r = rsqrtf(tot * (1.0f / ND) + 1e-6f);
    store_aug4(o, (size_t)row * 3 * ND, ND, threadIdx.x * 4, v.x*r, v.y*r, v.z*r, v.w*r);
}

// ------------------------- fp32 -> aug bf16 ---------------------------------
__global__ __launch_bounds__(256)
void split_kernel(const float* __restrict__ x, __nv_bfloat16* __restrict__ o) {
    int row = blockIdx.x;
    float4 v = ((const float4*)(x + (size_t)row * ND))[threadIdx.x];
    store_aug4(o, (size_t)row * 3 * ND, ND, threadIdx.x * 4, v.x, v.y, v.z, v.w);
}

// ------------------- weight transpose + split (K,N)->(N,3K) -----------------
__global__ __launch_bounds__(1024)
void transpose_split_kernel(const float* __restrict__ B, __nv_bfloat16* __restrict__ out,
                            int K, int N) {
    __shared__ float sm[64][33];
    int k0 = blockIdx.x * 64, n0 = blockIdx.y * 32;
    int tx = threadIdx.x, ty = threadIdx.y;        // 32x32
    int lin = ty * 32 + tx;
    #pragma unroll
    for (int e = 0; e < 2; e++) {
        int idx = lin + e * 1024;
        int kk = idx >> 5, nn = idx & 31;
        sm[kk][nn] = B[(size_t)(k0 + kk) * N + n0 + nn];
    }
    __syncthreads();
    int n = n0 + ty;
    int kk = 2 * tx;
    float v0 = sm[kk][ty], v1 = sm[kk + 1][ty];
    __nv_bfloat16 h0, l0, h1, l1;
    split_hi_lo(v0, h0, l0); split_hi_lo(v1, h1, l1);
    size_t base = (size_t)n * 3 * K;
    __nv_bfloat162 p;
    p.x = h0; p.y = h1;
    *(__nv_bfloat162*)(out + base + k0 + kk) = p;
    *(__nv_bfloat162*)(out + base + K + k0 + kk) = p;
    p.x = l0; p.y = l1;
    *(__nv_bfloat162*)(out + base + 2 * K + k0 + kk) = p;
}

// ----------------------- Householder Q (64x64) ------------------------------
__global__ void buildQ_kernel(const float* __restrict__ vs) {
    __shared__ float Qm[NHD][NHD];
    __shared__ float vv[NHD];
    int t = threadIdx.x;
    #pragma unroll
    for (int i = 0; i < NHD; i++) Qm[i][t] = (i == t) ? 1.f : 0.f;
    for (int r = 0; r < 32; r++) {
        __syncthreads();
        vv[t] = vs[r * NHD + t];
        __syncthreads();
        float w = 0.f, vn = 0.f;
        #pragma unroll
        for (int i = 0; i < NHD; i++) { w += vv[i] * Qm[i][t]; vn += vv[i] * vv[i]; }
        float c = 2.0f / (vn + 1e-8f);
        #pragma unroll
        for (int i = 0; i < NHD; i++) Qm[i][t] -= c * vv[i] * w;
    }
    __syncthreads();
    for (int i = 0; i < NHD; i++) g_Q[i * NHD + t] = Qm[i][t];
}

// ----------------------------- rope tables ----------------------------------
__global__ void rope_tables_kernel() {
    int s = blockIdx.x;
    int d = threadIdx.x;
    int i = d & 31;
    float invf = powf(10000.0f, -(float)(2 * i) / 64.0f);
    float ang = (float)s * invf;
    g_cos[s * NHD + d] = cosf(ang);
    g_sin[s * NHD + d] = sinf(ang);
}

// ------------- RnRoPE apply + head transpose (q,k rotated, v copied) --------
__global__ __launch_bounds__(256)
void rope_apply_kernel(const float* __restrict__ qkv) {
    int bs = blockIdx.x;
    int which = blockIdx.y;
    int b = bs >> 11, s = bs & 2047;
    int tid = threadIdx.x;
    int lane = tid & 63, grp = tid >> 6;

    if (which == 2) {
        #pragma unroll
        for (int hh = 0; hh < 4; hh++) {
            int h = grp * 4 + hh;
            g_vh[(((size_t)(b * NH + h)) * NS + s) * NHD + lane] =
                qkv[(size_t)bs * THREE_D + 2 * ND + h * NHD + lane];
        }
        return;
    }
    __shared__ float Qm[NHD][NHD + 1];
    __shared__ float xb[4][NHD];
    __shared__ float rb[4][NHD];
    __shared__ float cs[NHD], sn[NHD];
    for (int i = tid; i < NHD * NHD; i += 256) Qm[i >> 6][i & 63] = g_Q[i];
    if (tid < NHD) { cs[tid] = g_cos[s * NHD + tid]; sn[tid] = g_sin[s * NHD + tid]; }
    __syncthreads();
    const float* src = qkv + (size_t)bs * THREE_D + which * ND;
    float* dst = (which == 0) ? g_qh : g_kh;
    for (int hh = 0; hh < 4; hh++) {
        int h = grp * 4 + hh;
        xb[grp][lane] = src[h * NHD + lane];
        __syncthreads();
        float t = 0.f;
        #pragma unroll
        for (int j = 0; j < NHD; j++) t += xb[grp][j] * Qm[lane][j];
        rb[grp][lane] = t;
        __syncthreads();
        float rot = (lane < 32) ? -rb[grp][lane + 32] : rb[grp][lane - 32];
        float r = t * cs[lane] + rot * sn[lane];
        xb[grp][lane] = r;
        __syncthreads();
        float o = 0.f;
        #pragma unroll
        for (int j = 0; j < NHD; j++) o += xb[grp][j] * Qm[j][lane];
        dst[(((size_t)(b * NH + h)) * NS + s) * NHD + lane] = o;
        __syncthreads();
    }
}

// ------------------------------ flash attention -----------------------------
#define FL_STRIDE 68
#define FLASH_SMEM (4 * 64 * FL_STRIDE * 4)

__global__ __launch_bounds__(256)
void flash_kernel() {
    extern __shared__ float smf[];
    float* QsT = smf;
    float* KsT = smf + 64 * FL_STRIDE;
    float* Vs  = smf + 2 * 64 * FL_STRIDE;
    float* Ps  = smf + 3 * 64 * FL_STRIDE;

    const int qt = blockIdx.x;
    const int bh = blockIdx.y;
    const int b = bh >> 4, h = bh & 15;
    const int tid = threadIdx.x;
    const int ty = tid >> 4, tx = tid & 15;
    const int lr = tid >> 2;
    const int lc = (tid & 3) * 16;

    const float* qbase = g_qh + ((size_t)bh * NS + qt * 64) * NHD;
    const float* kbase = g_kh + (size_t)bh * NS * NHD;
    const float* vbase = g_vh + (size_t)bh * NS * NHD;

    #pragma unroll
    for (int v4 = 0; v4 < 4; v4++) {
        float4 q4 = *(const float4*)(qbase + lr * 64 + lc + v4 * 4);
        QsT[(lc + v4*4 + 0) * FL_STRIDE + lr] = q4.x;
        QsT[(lc + v4*4 + 1) * FL_STRIDE + lr] = q4.y;
        QsT[(lc + v4*4 + 2) * FL_STRIDE + lr] = q4.z;
        QsT[(lc + v4*4 + 3) * FL_STRIDE + lr] = q4.w;
    }

    float m[4], l[4], o[4][4];
    #pragma unroll
    for (int i = 0; i < 4; i++) {
        m[i] = -1e30f; l[i] = 0.f;
        #pragma unroll
        for (int j = 0; j < 4; j++) o[i][j] = 0.f;
    }

    const int nkv = ((qt >> 1) + 1) * 2;
    for (int kt = 0; kt < nkv; kt++) {
        __syncthreads();
        const float* kp = kbase + (size_t)kt * 64 * 64;
        const float* vp = vbase + (size_t)kt * 64 * 64;
        #pragma unroll
        for (int v4 = 0; v4 < 4; v4++) {
            float4 k4 = *(const float4*)(kp + lr * 64 + lc + v4 * 4);
            KsT[(lc + v4*4 + 0) * FL_STRIDE + lr] = k4.x;
            KsT[(lc + v4*4 + 1) * FL_STRIDE + lr] = k4.y;
            KsT[(lc + v4*4 + 2) * FL_STRIDE + lr] = k4.z;
            KsT[(lc + v4*4 + 3) * FL_STRIDE + lr] = k4.w;
            float4 vv4 = *(const float4*)(vp + lr * 64 + lc + v4 * 4);
            *(float4*)&Vs[lr * FL_STRIDE + lc + v4 * 4] = vv4;
        }
        __syncthreads();

        float s4[4][4];
        #pragma unroll
        for (int i = 0; i < 4; i++)
            #pragma unroll
            for (int j = 0; j < 4; j++) s4[i][j] = 0.f;

        #pragma unroll 8
        for (int d = 0; d < 64; d++) {
            float4 av = *(const float4*)&QsT[d * FL_STRIDE + ty * 4];
            float4 bv = *(const float4*)&KsT[d * FL_STRIDE + tx * 4];
            float a[4] = {av.x, av.y, av.z, av.w};
            float c[4] = {bv.x, bv.y, bv.z, bv.w};
            #pragma unroll
            for (int i = 0; i < 4; i++)
                #pragma unroll
                for (int j = 0; j < 4; j++)
                    s4[i][j] = fmaf(a[i], c[j], s4[i][j]);
        }

        const float scale = 0.125f;
        #pragma unroll
        for (int i = 0; i < 4; i++) {
            float mt = -1e30f;
            #pragma unroll
            for (int j = 0; j < 4; j++) { s4[i][j] *= scale; mt = fmaxf(mt, s4[i][j]); }
            #pragma unroll
            for (int msk = 8; msk > 0; msk >>= 1)
                mt = fmaxf(mt, __shfl_xor_sync(0xffffffffu, mt, msk));
            float mn = fmaxf(m[i], mt);
            float alpha = __expf(m[i] - mn);
            m[i] = mn;
            float lt = 0.f;
            #pragma unroll
            for (int j = 0; j < 4; j++) {
                float p = __expf(s4[i][j] - mn);
                s4[i][j] = p; lt += p;
            }
            #pragma unroll
            for (int msk = 8; msk > 0; msk >>= 1)
                lt += __shfl_xor_sync(0xffffffffu, lt, msk);
            l[i] = l[i] * alpha + lt;
            #pragma unroll
            for (int j = 0; j < 4; j++) o[i][j] *= alpha;
            float4 pw = make_float4(s4[i][0], s4[i][1], s4[i][2], s4[i][3]);
            *(float4*)&Ps[(ty * 4 + i) * FL_STRIDE + tx * 4] = pw;
        }
        __syncthreads();

        #pragma unroll 8
        for (int n = 0; n < 64; n++) {
            float4 vv = *(const float4*)&Vs[n * FL_STRIDE + tx * 4];
            float c[4] = {vv.x, vv.y, vv.z, vv.w};
            float pa[4];
            #pragma unroll
            for (int i = 0; i < 4; i++) pa[i] = Ps[(ty * 4 + i) * FL_STRIDE + n];
            #pragma unroll
            for (int i = 0; i < 4; i++)
                #pragma unroll
                for (int j = 0; j < 4; j++)
                    o[i][j] = fmaf(pa[i], c[j], o[i][j]);
        }
    }

    const int s0 = qt * 64;
    #pragma unroll
    for (int i = 0; i < 4; i++) {
        float inv = 1.f / l[i];
        int srow = s0 + ty * 4 + i;
        int row = b * NS + srow;
        store_aug4(g_attn_aug, (size_t)row * 3 * ND, ND, h * 64 + tx * 4,
                   o[i][0]*inv, o[i][1]*inv, o[i][2]*inv, o[i][3]*inv);
    }
}

// ====================== HMMA bf16 GEMM (mma.sync) ===========================
// C[M,N] = A_aug[M,Kp] @ Bt_aug[N,Kp]^T  (fp32 accum)
// BM=BN=128, BK=32, 3-stage cp.async pipeline, 8 warps (2x4), 64x32 warp tile.
// EPI 0: +bias (optional)  EPI 1: C = e2 + e1*sigmoid(acc+bias)  EPI 2: C = e2+acc+bias
#define HG_PAD    40                      // bf16 per smem row (80 B)
#define HG_STAGE  (2 * 128 * HG_PAD * 2)  // A+B per stage = 20480 B
#define HG_SMEM   (3 * HG_STAGE)          // 61440 B

template<int EPI>
__global__ __launch_bounds__(256)
void hmma_gemm(const __nv_bfloat16* __restrict__ A, const __nv_bfloat16* __restrict__ Bt,
               float* __restrict__ C, int M, int N, int Kp,
               const float* __restrict__ bias,
               const float* __restrict__ e1, const float* __restrict__ e2)
{
    extern __shared__ char smc[];
    const int tid = threadIdx.x;
    const int wid = tid >> 5, lane = tid & 31;
    const int m0 = blockIdx.y * 128, n0 = blockIdx.x * 128;
    const int wm = (wid >> 2) * 64, wn = (wid & 3) * 32;
    const uint32_t sbase = smem_u32(smc);

    // per-thread load coords: 512 16B-chunks for A, 512 for B; 4 chunks/thread
    const int q0 = tid, q1 = tid + 256;
    const int ra0 = q0 >> 2, ca0 = (q0 & 3);
    const int ra1 = q1 >> 2, ca1 = (q1 & 3);

    auto load_stage = [&](int s, int kk) {
        uint32_t aS = sbase + s * HG_STAGE;
        uint32_t bS = aS + 128 * HG_PAD * 2;
        cp_async16(aS + ra0 * 80 + ca0 * 16, A + (size_t)(m0 + ra0) * Kp + kk + ca0 * 8);
        cp_async16(aS + ra1 * 80 + ca1 * 16, A + (size_t)(m0 + ra1) * Kp + kk + ca1 * 8);
        cp_async16(bS + ra0 * 80 + ca0 * 16, Bt + (size_t)(n0 + ra0) * Kp + kk + ca0 * 8);
        cp_async16(bS + ra1 * 80 + ca1 * 16, Bt + (size_t)(n0 + ra1) * Kp + kk + ca1 * 8);
        CP_COMMIT();
    };

    const int KT = Kp >> 5;
    load_stage(0, 0);
    load_stage(1, 32);

    float acc[16][4];
    #pragma unroll
    for (int f = 0; f < 16; f++)
        #pragma unroll
        for (int e = 0; e < 4; e++) acc[f][e] = 0.f;

    // ldmatrix lane addressing (constant across iterations)
    const int a_r = (lane & 15);           // row within 16
    const int a_c = (lane >> 4) * 8;       // k offset 0/8
    const int b_g = lane >> 3;
    const int b_r = (b_g >> 1) * 8 + (lane & 7);
    const int b_c = (b_g & 1) * 8;

    for (int kt = 0; kt < KT; kt++) {
        CP_WAIT1();
        __syncthreads();
        if (kt + 2 < KT) load_stage((kt + 2) % 3, (kt + 2) * 32);

        uint32_t aS = sbase + (kt % 3) * HG_STAGE;
        uint32_t bS = aS + 128 * HG_PAD * 2;

        #pragma unroll
        for (int ks = 0; ks < 2; ks++) {
            uint32_t af[4][4];
            #pragma unroll
            for (int mf = 0; mf < 4; mf++) {
                uint32_t addr = aS + (uint32_t)((wm + mf * 16 + a_r) * 80 + (ks * 16 + a_c) * 2);
                ldsm_x4(af[mf][0], af[mf][1], af[mf][2], af[mf][3], addr);
            }
            uint32_t bfr[2][4];
            #pragma unroll
            for (int nb = 0; nb < 2; nb++) {
                uint32_t addr = bS + (uint32_t)((wn + nb * 16 + b_r) * 80 + (ks * 16 + b_c) * 2);
                ldsm_x4(bfr[nb][0], bfr[nb][1], bfr[nb][2], bfr[nb][3], addr);
            }
            #pragma unroll
            for (int mf = 0; mf < 4; mf++)
                #pragma unroll
                for (int nf = 0; nf < 4; nf++) {
                    int nb = nf >> 1, pr = (nf & 1) * 2;
                    mma16816(acc[mf * 4 + nf], af[mf], bfr[nb][pr], bfr[nb][pr + 1]);
                }
        }
    }

    // epilogue: direct register -> gmem
    #pragma unroll
    for (int mf = 0; mf < 4; mf++) {
        #pragma unroll
        for (int nf = 0; nf < 4; nf++) {
            float* a = acc[mf * 4 + nf];
            int col = n0 + wn + nf * 8 + (lane & 3) * 2;
            #pragma unroll
            for (int half = 0; half < 2; half++) {
                int row = m0 + wm + mf * 16 + (lane >> 2) + half * 8;
                size_t idx = (size_t)row * N + col;
                float v0 = a[half * 2], v1 = a[half * 2 + 1];
                if (EPI == 0) {
                    if (bias) { v0 += bias[col]; v1 += bias[col + 1]; }
                    *(float2*)(C + idx) = make_float2(v0, v1);
                } else if (EPI == 1) {
                    float g0 = 1.f / (1.f + __expf(-(v0 + bias[col])));
                    float g1 = 1.f / (1.f + __expf(-(v1 + bias[col + 1])));
                    float2 ee1 = *(const float2*)(e1 + idx);
                    float2 ee2 = *(const float2*)(e2 + idx);
                    *(float2*)(C + idx) = make_float2(ee2.x + ee1.x * g0, ee2.y + ee1.y * g1);
                } else {
                    float2 ee2 = *(const float2*)(e2 + idx);
                    *(float2*)(C + idx) = make_float2(ee2.x + v0 + bias[col],
                                                      ee2.y + v1 + bias[col + 1]);
                }
            }
        }
    }
}

// ------------------------- GLU (exact gelu) -> aug --------------------------
__global__ __launch_bounds__(256)
void glu_split_kernel(const float* __restrict__ gv, __nv_bfloat16* __restrict__ t) {
    size_t idx = (size_t)blockIdx.x * 256 + threadIdx.x;
    size_t row = idx >> 10;
    size_t col4 = idx & 1023;
    float4 g4 = ((const float4*)(gv + row * 8 * ND))[col4];
    float4 v4 = ((const float4*)(gv + row * 8 * ND + 4 * ND))[col4];
    const float kc = 0.70710678118654752f;
    float o0 = v4.x * (0.5f * g4.x * (1.f + erff(g4.x * kc)));
    float o1 = v4.y * (0.5f * g4.y * (1.f + erff(g4.y * kc)));
    float o2 = v4.z * (0.5f * g4.z * (1.f + erff(g4.z * kc)));
    float o3 = v4.w * (0.5f * g4.w * (1.f + erff(g4.w * kc)));
    store_aug4(t, row * 12 * ND, 4 * ND, (int)col4 * 4, o0, o1, o2, o3);
}

// --------------------------------- launcher ---------------------------------
extern "C" void kernel_launch(void* const* d_in, const int* in_sizes, int n_in,
                              void* d_out, int out_size) {
    const float* x          = (const float*)d_in[0];
    const float* vs         = (const float*)d_in[3];
    const float* w_qkv      = (const float*)d_in[4];
    const float* w_out      = (const float*)d_in[5];
    const float* w_gate     = (const float*)d_in[6];
    const float* b_gate     = (const float*)d_in[7];
    const float* w_mlp_gate = (const float*)d_in[8];
    const float* b_mlp_gate = (const float*)d_in[9];
    const float* w_mlp_out  = (const float*)d_in[10];
    const float* b_mlp_out  = (const float*)d_in[11];
    float* out = (float*)d_out;

    float *p_qkv, *p_attnproj, *p_x1, *p_gv;
    __nv_bfloat16 *p_h_aug, *p_attn_aug, *p_ap_aug, *p_h2_aug, *p_t_aug;
    __nv_bfloat16 *p_wqkvT, *p_woutT, *p_wgateT, *p_wmgT, *p_wmoT;
    cudaGetSymbolAddress((void**)&p_qkv, g_qkv);
    cudaGetSymbolAddress((void**)&p_attnproj, g_attnproj);
    cudaGetSymbolAddress((void**)&p_x1, g_x1);
    cudaGetSymbolAddress((void**)&p_gv, g_gv);
    cudaGetSymbolAddress((void**)&p_h_aug, g_h_aug);
    cudaGetSymbolAddress((void**)&p_attn_aug, g_attn_aug);
    cudaGetSymbolAddress((void**)&p_ap_aug, g_ap_aug);
    cudaGetSymbolAddress((void**)&p_h2_aug, g_h2_aug);
    cudaGetSymbolAddress((void**)&p_t_aug, g_t_aug);
    cudaGetSymbolAddress((void**)&p_wqkvT, g_wqkvT);
    cudaGetSymbolAddress((void**)&p_woutT, g_woutT);
    cudaGetSymbolAddress((void**)&p_wgateT, g_wgateT);
    cudaGetSymbolAddress((void**)&p_wmgT, g_wmgT);
    cudaGetSymbolAddress((void**)&p_wmoT, g_wmoT);

    cudaFuncSetAttribute(flash_kernel, cudaFuncAttributeMaxDynamicSharedMemorySize, FLASH_SMEM);
    cudaFuncSetAttribute(hmma_gemm<0>, cudaFuncAttributeMaxDynamicSharedMemorySize, HG_SMEM);
    cudaFuncSetAttribute(hmma_gemm<1>, cudaFuncAttributeMaxDynamicSharedMemorySize, HG_SMEM);
    cudaFuncSetAttribute(hmma_gemm<2>, cudaFuncAttributeMaxDynamicSharedMemorySize, HG_SMEM);

    dim3 t32(32, 32);
    transpose_split_kernel<<<dim3(ND/64, THREE_D/32), t32>>>(w_qkv, p_wqkvT, ND, THREE_D);
    transpose_split_kernel<<<dim3(ND/64, ND/32), t32>>>(w_out, p_woutT, ND, ND);
    transpose_split_kernel<<<dim3(ND/64, ND/32), t32>>>(w_gate, p_wgateT, ND, ND);
    transpose_split_kernel<<<dim3(ND/64, 8*ND/32), t32>>>(w_mlp_gate, p_wmgT, ND, 8*ND);
    transpose_split_kernel<<<dim3(4*ND/64, ND/32), t32>>>(w_mlp_out, p_wmoT, 4*ND, ND);

    buildQ_kernel<<<1, 64>>>(vs);
    rope_tables_kernel<<<NS, 64>>>();

    // 1. h_aug = split(rmsnorm(x))
    rmsnorm_split_kernel<<<NBS, 256>>>(x, p_h_aug);
    // 2. qkv = h @ w_qkv
    hmma_gemm<0><<<dim3(THREE_D/128, NBS/128), 256, HG_SMEM>>>(
        p_h_aug, p_wqkvT, p_qkv, NBS, THREE_D, 3*ND, nullptr, nullptr, nullptr);
    // 3. RnRoPE + head transpose
    rope_apply_kernel<<<dim3(NBS, 3), 256>>>(p_qkv);
    // 4. attention -> attn_aug
    flash_kernel<<<dim3(NS/64, NB*NH), 256, FLASH_SMEM>>>();
    // 5. attnproj = attn @ w_out
    hmma_gemm<0><<<dim3(ND/128, NBS/128), 256, HG_SMEM>>>(
        p_attn_aug, p_woutT, p_attnproj, NBS, ND, 3*ND, nullptr, nullptr, nullptr);
    // 6. split attnproj
    split_kernel<<<NBS, 256>>>(p_attnproj, p_ap_aug);
    // 7. x1 = x + attnproj * sigmoid(attnproj @ w_gate + b_gate)
    hmma_gemm<1><<<dim3(ND/128, NBS/128), 256, HG_SMEM>>>(
        p_ap_aug, p_wgateT, p_x1, NBS, ND, 3*ND, b_gate, p_attnproj, x);
    // 8. h2_aug = split(rmsnorm(x1))
    rmsnorm_split_kernel<<<NBS, 256>>>(p_x1, p_h2_aug);
    // 9. gv = h2 @ w_mlp_gate + b
    hmma_gemm<0><<<dim3(8*ND/128, NBS/128), 256, HG_SMEM>>>(
        p_h2_aug, p_wmgT, p_gv, NBS, 8*ND, 3*ND, b_mlp_gate, nullptr, nullptr);
    // 10. t_aug = split(val * gelu(g))
    glu_split_kernel<<<(NBS * 4 * ND / 4) / 256, 256>>>(p_gv, p_t_aug);
    // 11. out = x1 + t @ w_mlp_out + b
    hmma_gemm<2><<<dim3(ND/128, NBS/128), 256, HG_SMEM>>>(
        p_t_aug, p_wmoT, out, NBS, ND, 12*ND, b_mlp_out, nullptr, p_x1);
}